// round 1
// baseline (speedup 1.0000x reference)
#include <cuda_runtime.h>

// Problem constants
#define Bq   8
#define Nn   1024
#define DIN  256
#define DOUT 256
#define Rr   4

// ---------------- scratch (static device globals; no allocation) -------------
__device__ float g_feats[(size_t)Bq * Rr * Nn * DOUT];          // 32 MB
__device__ float g_si[Bq * Rr * Nn];
__device__ float g_sj[Bq * Rr * Nn];
__device__ float g_attn[(size_t)Bq * Rr * Nn * Nn];             // 128 MB

// ---------------- block reductions (blockDim.x == 256) -----------------------
__device__ __forceinline__ float blockReduceMax256(float v, float* red) {
    int lane = threadIdx.x & 31;
    #pragma unroll
    for (int o = 16; o; o >>= 1) v = fmaxf(v, __shfl_xor_sync(0xffffffffu, v, o));
    if (lane == 0) red[threadIdx.x >> 5] = v;
    __syncthreads();
    if (threadIdx.x < 32) {
        float r = (threadIdx.x < 8) ? red[threadIdx.x] : -3.4e38f;
        #pragma unroll
        for (int o = 4; o; o >>= 1) r = fmaxf(r, __shfl_xor_sync(0xffffffffu, r, o));
        if (threadIdx.x == 0) red[0] = r;
    }
    __syncthreads();
    float out = red[0];
    __syncthreads();
    return out;
}

__device__ __forceinline__ float blockReduceSum256(float v, float* red) {
    int lane = threadIdx.x & 31;
    #pragma unroll
    for (int o = 16; o; o >>= 1) v += __shfl_xor_sync(0xffffffffu, v, o);
    if (lane == 0) red[threadIdx.x >> 5] = v;
    __syncthreads();
    if (threadIdx.x < 32) {
        float r = (threadIdx.x < 8) ? red[threadIdx.x] : 0.0f;
        #pragma unroll
        for (int o = 4; o; o >>= 1) r += __shfl_xor_sync(0xffffffffu, r, o);
        if (threadIdx.x == 0) red[0] = r;
    }
    __syncthreads();
    float out = red[0];
    __syncthreads();
    return out;
}

// ============================================================================
// Kernel A: feats[b,r,n,d] = x[b,n,:] . rel_w[r,d,:] + rel_b[r,d]
// NT GEMM, tile 128(M=n) x 64(N=d) x 16(K), 256 threads, TM=8, TN=4
// grid: (4 d-tiles, 8 n-tiles, B*R)
// ============================================================================
__global__ __launch_bounds__(256) void feats_kernel(
    const float* __restrict__ x, const float* __restrict__ rw,
    const float* __restrict__ rb)
{
    const int br = blockIdx.z;
    const int b = br / Rr, r = br % Rr;
    const int n0 = blockIdx.y * 128;
    const int d0 = blockIdx.x * 64;

    __shared__ float As[16][128];
    __shared__ float Bs[16][64];

    const int tid = threadIdx.x;
    const int ty = tid / 16, tx = tid % 16;

    const float* A  = x  + (size_t)b * Nn * DIN;    // [1024][256] row-major
    const float* Bm = rw + (size_t)r * DOUT * DIN;  // [256][256]  row-major (d,k)

    float acc[8][4] = {};

    const int ar = tid / 4;            // 0..63
    const int ac = (tid % 4) * 4;      // 0,4,8,12
    const int brr = tid / 4;           // 0..63  (d within tile)
    const int bc  = (tid % 4) * 4;

    for (int kt = 0; kt < DIN; kt += 16) {
        #pragma unroll
        for (int h = 0; h < 2; h++) {
            float4 v = *(const float4*)&A[(size_t)(n0 + ar + h * 64) * DIN + kt + ac];
            As[ac + 0][ar + h * 64] = v.x;
            As[ac + 1][ar + h * 64] = v.y;
            As[ac + 2][ar + h * 64] = v.z;
            As[ac + 3][ar + h * 64] = v.w;
        }
        {
            float4 v = *(const float4*)&Bm[(size_t)(d0 + brr) * DIN + kt + bc];
            Bs[bc + 0][brr] = v.x;
            Bs[bc + 1][brr] = v.y;
            Bs[bc + 2][brr] = v.z;
            Bs[bc + 3][brr] = v.w;
        }
        __syncthreads();

        #pragma unroll
        for (int kk = 0; kk < 16; kk++) {
            float4 a0 = *(const float4*)&As[kk][ty * 8];
            float4 a1 = *(const float4*)&As[kk][ty * 8 + 4];
            float4 bb = *(const float4*)&Bs[kk][tx * 4];
            float av[8] = {a0.x, a0.y, a0.z, a0.w, a1.x, a1.y, a1.z, a1.w};
            float bv[4] = {bb.x, bb.y, bb.z, bb.w};
            #pragma unroll
            for (int i = 0; i < 8; i++)
                #pragma unroll
                for (int j = 0; j < 4; j++)
                    acc[i][j] = fmaf(av[i], bv[j], acc[i][j]);
        }
        __syncthreads();
    }

    float* F = g_feats + (size_t)br * Nn * DOUT;
    #pragma unroll
    for (int i = 0; i < 8; i++) {
        int n = n0 + ty * 8 + i;
        #pragma unroll
        for (int j = 0; j < 4; j++) {
            int d = d0 + tx * 4 + j;
            F[(size_t)n * DOUT + d] = acc[i][j] + rb[r * DOUT + d];
        }
    }
}

// ============================================================================
// Kernel A2: si/sj per (b,r,n) row — one warp per row
// ============================================================================
__global__ __launch_bounds__(256) void sisj_kernel(const float* __restrict__ attn_w)
{
    int warp = blockIdx.x * 8 + (threadIdx.x >> 5);   // 0 .. B*R*N-1
    int lane = threadIdx.x & 31;
    const float* f = g_feats + (size_t)warp * DOUT;
    float si = 0.f, sj = 0.f;
    #pragma unroll
    for (int i = lane; i < DOUT; i += 32) {
        float v = f[i];
        si = fmaf(v, attn_w[i], si);
        sj = fmaf(v, attn_w[DOUT + i], sj);
    }
    #pragma unroll
    for (int o = 16; o; o >>= 1) {
        si += __shfl_down_sync(0xffffffffu, si, o);
        sj += __shfl_down_sync(0xffffffffu, sj, o);
    }
    if (lane == 0) { g_si[warp] = si; g_sj[warp] = sj; }
}

// ============================================================================
// Kernel B: masked softmax rows. Block handles 16 rows of one (b,r).
// grid: B*R*(N/16) = 2048 blocks, 256 threads.
// ============================================================================
__global__ __launch_bounds__(256) void softmax_kernel(
    const int* __restrict__ adj, const float* __restrict__ attn_b_p)
{
    const int ROWS = 16;
    int br = blockIdx.x / (Nn / ROWS);
    int nt = blockIdx.x % (Nn / ROWS);

    __shared__ float sjs[Nn];
    __shared__ float red[8];

    float ab = attn_b_p[0];
    const float* sjp = g_sj + br * Nn;
    for (int m = threadIdx.x; m < Nn; m += 256) sjs[m] = sjp[m] + ab;
    __syncthreads();

    const int*   adjb = adj    + (size_t)br * Nn * Nn;
    float*       attb = g_attn + (size_t)br * Nn * Nn;
    const int tid = threadIdx.x;

    for (int rr = 0; rr < ROWS; rr++) {
        int n = nt * ROWS + rr;
        float si = g_si[br * Nn + n];
        const int* arow = adjb + (size_t)n * Nn;

        float v[4], mx = -3.4e38f;
        #pragma unroll
        for (int u = 0; u < 4; u++) {
            int m = tid + u * 256;
            v[u] = (arow[m] != 0) ? (si + sjs[m]) : -1e9f;
            mx = fmaxf(mx, v[u]);
        }
        mx = blockReduceMax256(mx, red);

        float p[4], s = 0.f;
        #pragma unroll
        for (int u = 0; u < 4; u++) { p[u] = __expf(v[u] - mx); s += p[u]; }
        s = blockReduceSum256(s, red);
        float inv = 1.0f / s;

        float* orow = attb + (size_t)n * Nn;
        #pragma unroll
        for (int u = 0; u < 4; u++) orow[tid + u * 256] = p[u] * inv;
    }
}

// ============================================================================
// Kernel C: agg[b,n,d] = sum_r attn[b,r,n,:] @ feats[b,r,:,d]
// tile 128(n) x 64(d) x 16, K total = R*N = 4096. grid (4, 8, B)
// writes agg straight into d_out
// ============================================================================
__global__ __launch_bounds__(256) void agg_kernel(float* __restrict__ out)
{
    const int b  = blockIdx.z;
    const int n0 = blockIdx.y * 128;
    const int d0 = blockIdx.x * 64;

    __shared__ float As[16][128];
    __shared__ float Bs[16][64];

    const int tid = threadIdx.x;
    const int ty = tid / 16, tx = tid % 16;

    float acc[8][4] = {};

    const int ar = tid / 4;
    const int ac = (tid % 4) * 4;
    const int bkr = tid / 16;          // 0..15 (k within tile)
    const int bcl = (tid % 16) * 4;    // 0..60 (d within tile)

    for (int r = 0; r < Rr; r++) {
        const float* A  = g_attn  + (size_t)(b * Rr + r) * Nn * Nn;   // [n][m]
        const float* Bm = g_feats + (size_t)(b * Rr + r) * Nn * DOUT; // [m][d]
        for (int kt = 0; kt < Nn; kt += 16) {
            #pragma unroll
            for (int h = 0; h < 2; h++) {
                float4 v = *(const float4*)&A[(size_t)(n0 + ar + h * 64) * Nn + kt + ac];
                As[ac + 0][ar + h * 64] = v.x;
                As[ac + 1][ar + h * 64] = v.y;
                As[ac + 2][ar + h * 64] = v.z;
                As[ac + 3][ar + h * 64] = v.w;
            }
            {
                float4 w = *(const float4*)&Bm[(size_t)(kt + bkr) * DOUT + d0 + bcl];
                *(float4*)&Bs[bkr][bcl] = w;
            }
            __syncthreads();

            #pragma unroll
            for (int kk = 0; kk < 16; kk++) {
                float4 a0 = *(const float4*)&As[kk][ty * 8];
                float4 a1 = *(const float4*)&As[kk][ty * 8 + 4];
                float4 bb = *(const float4*)&Bs[kk][tx * 4];
                float av[8] = {a0.x, a0.y, a0.z, a0.w, a1.x, a1.y, a1.z, a1.w};
                float bv[4] = {bb.x, bb.y, bb.z, bb.w};
                #pragma unroll
                for (int i = 0; i < 8; i++)
                    #pragma unroll
                    for (int j = 0; j < 4; j++)
                        acc[i][j] = fmaf(av[i], bv[j], acc[i][j]);
            }
            __syncthreads();
        }
    }

    #pragma unroll
    for (int i = 0; i < 8; i++) {
        int n = n0 + ty * 8 + i;
        #pragma unroll
        for (int j = 0; j < 4; j++) {
            int d = d0 + tx * 4 + j;
            out[((size_t)b * Nn + n) * DOUT + d] = acc[i][j];
        }
    }
}

// ============================================================================
// Kernel D: gate = sigmoid(agg . gate_w + gate_b); out = gate * agg (in place)
// one block (256 threads) per (b,n) row; D=256 -> one element per thread
// ============================================================================
__global__ __launch_bounds__(256) void gate_kernel(
    float* __restrict__ out, const float* __restrict__ gw,
    const float* __restrict__ gb_p)
{
    __shared__ float red[8];
    float* o = out + (size_t)blockIdx.x * DOUT;
    int t = threadIdx.x;
    float a = o[t];
    float s = blockReduceSum256(a * gw[t], red);
    float g = 1.0f / (1.0f + __expf(-(s + gb_p[0])));
    o[t] = g * a;
}

// ============================================================================
extern "C" void kernel_launch(void* const* d_in, const int* in_sizes, int n_in,
                              void* d_out, int out_size)
{
    const float* x   = (const float*)d_in[0];  // node_features [8,1024,256]
    const int*   adj = (const int*)  d_in[1];  // adj [8,4,1024,1024]
    const float* rw  = (const float*)d_in[2];  // rel_w [4,256,256]
    const float* rb  = (const float*)d_in[3];  // rel_b [4,256]
    const float* aw  = (const float*)d_in[4];  // attn_w [512]
    const float* ab  = (const float*)d_in[5];  // attn_b scalar
    const float* gw  = (const float*)d_in[6];  // gate_w [256]
    const float* gb  = (const float*)d_in[7];  // gate_b scalar
    float* out = (float*)d_out;                // [8,1024,256]

    dim3 gA(DOUT / 64, Nn / 128, Bq * Rr);
    feats_kernel<<<gA, 256>>>(x, rw, rb);

    sisj_kernel<<<(Bq * Rr * Nn) / 8, 256>>>(aw);

    softmax_kernel<<<Bq * Rr * (Nn / 16), 256>>>(adj, ab);

    dim3 gC(DOUT / 64, Nn / 128, Bq);
    agg_kernel<<<gC, 256>>>(out);

    gate_kernel<<<Bq * Nn, 256>>>(out, gw, gb);
}

// round 2
// speedup vs baseline: 1.0042x; 1.0042x over previous
#include <cuda_runtime.h>

// Problem constants
#define Bq   8
#define Nn   1024
#define DIN  256
#define DOUT 256
#define Rr   4

// ---------------- scratch (static device globals; no allocation) -------------
__device__ float g_feats[(size_t)Bq * Rr * Nn * DOUT];          // 32 MB
__device__ float g_si[Bq * Rr * Nn];
__device__ float g_sj[Bq * Rr * Nn];
__device__ float g_attn[(size_t)Bq * Rr * Nn * Nn];             // 128 MB

// ---------------- block reductions (blockDim.x == 256) -----------------------
__device__ __forceinline__ float blockReduceMax256(float v, float* red) {
    int lane = threadIdx.x & 31;
    #pragma unroll
    for (int o = 16; o; o >>= 1) v = fmaxf(v, __shfl_xor_sync(0xffffffffu, v, o));
    if (lane == 0) red[threadIdx.x >> 5] = v;
    __syncthreads();
    if (threadIdx.x < 32) {
        float r = (threadIdx.x < 8) ? red[threadIdx.x] : -3.4e38f;
        #pragma unroll
        for (int o = 4; o; o >>= 1) r = fmaxf(r, __shfl_xor_sync(0xffffffffu, r, o));
        if (threadIdx.x == 0) red[0] = r;
    }
    __syncthreads();
    float out = red[0];
    __syncthreads();
    return out;
}

__device__ __forceinline__ float blockReduceSum256(float v, float* red) {
    int lane = threadIdx.x & 31;
    #pragma unroll
    for (int o = 16; o; o >>= 1) v += __shfl_xor_sync(0xffffffffu, v, o);
    if (lane == 0) red[threadIdx.x >> 5] = v;
    __syncthreads();
    if (threadIdx.x < 32) {
        float r = (threadIdx.x < 8) ? red[threadIdx.x] : 0.0f;
        #pragma unroll
        for (int o = 4; o; o >>= 1) r += __shfl_xor_sync(0xffffffffu, r, o);
        if (threadIdx.x == 0) red[0] = r;
    }
    __syncthreads();
    float out = red[0];
    __syncthreads();
    return out;
}

// ============================================================================
// Kernel A: feats[b,r,n,d] = x[b,n,:] . rel_w[r,d,:] + rel_b[r,d]
// NT GEMM, tile 128(M=n) x 64(N=d) x 16(K), 256 threads, TM=8, TN=4
// grid: (4 d-tiles, 8 n-tiles, B*R)
// ============================================================================
__global__ __launch_bounds__(256) void feats_kernel(
    const float* __restrict__ x, const float* __restrict__ rw,
    const float* __restrict__ rb)
{
    const int br = blockIdx.z;
    const int b = br / Rr, r = br % Rr;
    const int n0 = blockIdx.y * 128;
    const int d0 = blockIdx.x * 64;

    __shared__ float As[16][128];
    __shared__ float Bs[16][64];

    const int tid = threadIdx.x;
    const int ty = tid / 16, tx = tid % 16;

    const float* A  = x  + (size_t)b * Nn * DIN;    // [1024][256] row-major
    const float* Bm = rw + (size_t)r * DOUT * DIN;  // [256][256]  row-major (d,k)

    float acc[8][4] = {};

    const int ar = tid / 4;            // 0..63
    const int ac = (tid % 4) * 4;      // 0,4,8,12
    const int brr = tid / 4;           // 0..63  (d within tile)
    const int bc  = (tid % 4) * 4;

    for (int kt = 0; kt < DIN; kt += 16) {
        #pragma unroll
        for (int h = 0; h < 2; h++) {
            float4 v = *(const float4*)&A[(size_t)(n0 + ar + h * 64) * DIN + kt + ac];
            As[ac + 0][ar + h * 64] = v.x;
            As[ac + 1][ar + h * 64] = v.y;
            As[ac + 2][ar + h * 64] = v.z;
            As[ac + 3][ar + h * 64] = v.w;
        }
        {
            float4 v = *(const float4*)&Bm[(size_t)(d0 + brr) * DIN + kt + bc];
            Bs[bc + 0][brr] = v.x;
            Bs[bc + 1][brr] = v.y;
            Bs[bc + 2][brr] = v.z;
            Bs[bc + 3][brr] = v.w;
        }
        __syncthreads();

        #pragma unroll
        for (int kk = 0; kk < 16; kk++) {
            float4 a0 = *(const float4*)&As[kk][ty * 8];
            float4 a1 = *(const float4*)&As[kk][ty * 8 + 4];
            float4 bb = *(const float4*)&Bs[kk][tx * 4];
            float av[8] = {a0.x, a0.y, a0.z, a0.w, a1.x, a1.y, a1.z, a1.w};
            float bv[4] = {bb.x, bb.y, bb.z, bb.w};
            #pragma unroll
            for (int i = 0; i < 8; i++)
                #pragma unroll
                for (int j = 0; j < 4; j++)
                    acc[i][j] = fmaf(av[i], bv[j], acc[i][j]);
        }
        __syncthreads();
    }

    float* F = g_feats + (size_t)br * Nn * DOUT;
    #pragma unroll
    for (int i = 0; i < 8; i++) {
        int n = n0 + ty * 8 + i;
        #pragma unroll
        for (int j = 0; j < 4; j++) {
            int d = d0 + tx * 4 + j;
            F[(size_t)n * DOUT + d] = acc[i][j] + rb[r * DOUT + d];
        }
    }
}

// ============================================================================
// Kernel A2: si/sj per (b,r,n) row — one warp per row
// ============================================================================
__global__ __launch_bounds__(256) void sisj_kernel(const float* __restrict__ attn_w)
{
    int warp = blockIdx.x * 8 + (threadIdx.x >> 5);   // 0 .. B*R*N-1
    int lane = threadIdx.x & 31;
    const float* f = g_feats + (size_t)warp * DOUT;
    float si = 0.f, sj = 0.f;
    #pragma unroll
    for (int i = lane; i < DOUT; i += 32) {
        float v = f[i];
        si = fmaf(v, attn_w[i], si);
        sj = fmaf(v, attn_w[DOUT + i], sj);
    }
    #pragma unroll
    for (int o = 16; o; o >>= 1) {
        si += __shfl_down_sync(0xffffffffu, si, o);
        sj += __shfl_down_sync(0xffffffffu, sj, o);
    }
    if (lane == 0) { g_si[warp] = si; g_sj[warp] = sj; }
}

// ============================================================================
// Kernel B: masked softmax rows. Block handles 16 rows of one (b,r).
// grid: B*R*(N/16) = 2048 blocks, 256 threads.
// ============================================================================
__global__ __launch_bounds__(256) void softmax_kernel(
    const int* __restrict__ adj, const float* __restrict__ attn_b_p)
{
    const int ROWS = 16;
    int br = blockIdx.x / (Nn / ROWS);
    int nt = blockIdx.x % (Nn / ROWS);

    __shared__ float sjs[Nn];
    __shared__ float red[8];

    float ab = attn_b_p[0];
    const float* sjp = g_sj + br * Nn;
    for (int m = threadIdx.x; m < Nn; m += 256) sjs[m] = sjp[m] + ab;
    __syncthreads();

    const int*   adjb = adj    + (size_t)br * Nn * Nn;
    float*       attb = g_attn + (size_t)br * Nn * Nn;
    const int tid = threadIdx.x;

    for (int rr = 0; rr < ROWS; rr++) {
        int n = nt * ROWS + rr;
        float si = g_si[br * Nn + n];
        const int* arow = adjb + (size_t)n * Nn;

        float v[4], mx = -3.4e38f;
        #pragma unroll
        for (int u = 0; u < 4; u++) {
            int m = tid + u * 256;
            v[u] = (arow[m] != 0) ? (si + sjs[m]) : -1e9f;
            mx = fmaxf(mx, v[u]);
        }
        mx = blockReduceMax256(mx, red);

        float p[4], s = 0.f;
        #pragma unroll
        for (int u = 0; u < 4; u++) { p[u] = __expf(v[u] - mx); s += p[u]; }
        s = blockReduceSum256(s, red);
        float inv = 1.0f / s;

        float* orow = attb + (size_t)n * Nn;
        #pragma unroll
        for (int u = 0; u < 4; u++) orow[tid + u * 256] = p[u] * inv;
    }
}

// ============================================================================
// Kernel C: agg[b,n,d] = sum_r attn[b,r,n,:] @ feats[b,r,:,d]
// tile 128(n) x 64(d) x 16, K total = R*N = 4096. grid (4, 8, B)
// writes agg straight into d_out
// ============================================================================
__global__ __launch_bounds__(256) void agg_kernel(float* __restrict__ out)
{
    const int b  = blockIdx.z;
    const int n0 = blockIdx.y * 128;
    const int d0 = blockIdx.x * 64;

    __shared__ float As[16][128];
    __shared__ float Bs[16][64];

    const int tid = threadIdx.x;
    const int ty = tid / 16, tx = tid % 16;

    float acc[8][4] = {};

    const int ar = tid / 4;
    const int ac = (tid % 4) * 4;
    const int bkr = tid / 16;          // 0..15 (k within tile)
    const int bcl = (tid % 16) * 4;    // 0..60 (d within tile)

    for (int r = 0; r < Rr; r++) {
        const float* A  = g_attn  + (size_t)(b * Rr + r) * Nn * Nn;   // [n][m]
        const float* Bm = g_feats + (size_t)(b * Rr + r) * Nn * DOUT; // [m][d]
        for (int kt = 0; kt < Nn; kt += 16) {
            #pragma unroll
            for (int h = 0; h < 2; h++) {
                float4 v = *(const float4*)&A[(size_t)(n0 + ar + h * 64) * Nn + kt + ac];
                As[ac + 0][ar + h * 64] = v.x;
                As[ac + 1][ar + h * 64] = v.y;
                As[ac + 2][ar + h * 64] = v.z;
                As[ac + 3][ar + h * 64] = v.w;
            }
            {
                float4 w = *(const float4*)&Bm[(size_t)(kt + bkr) * DOUT + d0 + bcl];
                *(float4*)&Bs[bkr][bcl] = w;
            }
            __syncthreads();

            #pragma unroll
            for (int kk = 0; kk < 16; kk++) {
                float4 a0 = *(const float4*)&As[kk][ty * 8];
                float4 a1 = *(const float4*)&As[kk][ty * 8 + 4];
                float4 bb = *(const float4*)&Bs[kk][tx * 4];
                float av[8] = {a0.x, a0.y, a0.z, a0.w, a1.x, a1.y, a1.z, a1.w};
                float bv[4] = {bb.x, bb.y, bb.z, bb.w};
                #pragma unroll
                for (int i = 0; i < 8; i++)
                    #pragma unroll
                    for (int j = 0; j < 4; j++)
                        acc[i][j] = fmaf(av[i], bv[j], acc[i][j]);
            }
            __syncthreads();
        }
    }

    #pragma unroll
    for (int i = 0; i < 8; i++) {
        int n = n0 + ty * 8 + i;
        #pragma unroll
        for (int j = 0; j < 4; j++) {
            int d = d0 + tx * 4 + j;
            out[((size_t)b * Nn + n) * DOUT + d] = acc[i][j];
        }
    }
}

// ============================================================================
// Kernel D: gate = sigmoid(agg . gate_w + gate_b); out = gate * agg (in place)
// one block (256 threads) per (b,n) row; D=256 -> one element per thread
// ============================================================================
__global__ __launch_bounds__(256) void gate_kernel(
    float* __restrict__ out, const float* __restrict__ gw,
    const float* __restrict__ gb_p)
{
    __shared__ float red[8];
    float* o = out + (size_t)blockIdx.x * DOUT;
    int t = threadIdx.x;
    float a = o[t];
    float s = blockReduceSum256(a * gw[t], red);
    float g = 1.0f / (1.0f + __expf(-(s + gb_p[0])));
    o[t] = g * a;
}

// ============================================================================
extern "C" void kernel_launch(void* const* d_in, const int* in_sizes, int n_in,
                              void* d_out, int out_size)
{
    const float* x   = (const float*)d_in[0];  // node_features [8,1024,256]
    const int*   adj = (const int*)  d_in[1];  // adj [8,4,1024,1024]
    const float* rw  = (const float*)d_in[2];  // rel_w [4,256,256]
    const float* rb  = (const float*)d_in[3];  // rel_b [4,256]
    const float* aw  = (const float*)d_in[4];  // attn_w [512]
    const float* ab  = (const float*)d_in[5];  // attn_b scalar
    const float* gw  = (const float*)d_in[6];  // gate_w [256]
    const float* gb  = (const float*)d_in[7];  // gate_b scalar
    float* out = (float*)d_out;                // [8,1024,256]

    dim3 gA(DOUT / 64, Nn / 128, Bq * Rr);
    feats_kernel<<<gA, 256>>>(x, rw, rb);

    sisj_kernel<<<(Bq * Rr * Nn) / 8, 256>>>(aw);

    softmax_kernel<<<Bq * Rr * (Nn / 16), 256>>>(adj, ab);

    dim3 gC(DOUT / 64, Nn / 128, Bq);
    agg_kernel<<<gC, 256>>>(out);

    gate_kernel<<<Bq * Nn, 256>>>(out, gw, gb);
}

// round 4
// speedup vs baseline: 2.5629x; 2.5523x over previous
#include <cuda_runtime.h>
#include <cuda_bf16.h>
#include <cstdint>

#define Bq   8
#define Nn   1024
#define DIN  256
#define DOUT 256
#define Rr   4

// ------------------------- scratch globals ----------------------------------
__device__ __nv_bfloat16 g_xh[(size_t)Bq * Nn * DIN];
__device__ __nv_bfloat16 g_xl[(size_t)Bq * Nn * DIN];
__device__ __nv_bfloat16 g_rwh[(size_t)Rr * DOUT * DIN];
__device__ __nv_bfloat16 g_rwl[(size_t)Rr * DOUT * DIN];
__device__ float         g_feats[(size_t)Bq * Rr * Nn * DOUT];   // 32 MB
__device__ float         g_w[Bq * Rr * Nn];
__device__ float         g_invZ[Bq * Rr * Nn];
__device__ __nv_bfloat16 g_wfh[(size_t)Bq * Rr * DOUT * Nn];     // wf^T hi [br][d][m]
__device__ __nv_bfloat16 g_wfl[(size_t)Bq * Rr * DOUT * Nn];     // wf^T lo
__device__ __nv_bfloat16 g_adjbf[(size_t)Bq * Rr * Nn * Nn];     // 64 MB

// ------------------------- helpers ------------------------------------------
__device__ __forceinline__ uint32_t smem_u32(const void* p) {
    uint32_t a;
    asm("{ .reg .u64 t; cvta.to.shared.u64 t, %1; cvt.u32.u64 %0, t; }"
        : "=r"(a) : "l"(p));
    return a;
}
#define CP_ASYNC16(dst, src) asm volatile("cp.async.cg.shared.global [%0], [%1], 16;" :: "r"(dst), "l"(src))
#define CP_COMMIT()          asm volatile("cp.async.commit_group;" ::: "memory")
#define CP_WAIT1()           asm volatile("cp.async.wait_group 1;" ::: "memory")
#define CP_WAIT0()           asm volatile("cp.async.wait_group 0;" ::: "memory")

__device__ __forceinline__ uint32_t sw128(uint32_t off) {
    return off ^ ((off >> 3) & 0x70);
}
__device__ __forceinline__ void ldsm4(uint32_t& r0, uint32_t& r1,
                                      uint32_t& r2, uint32_t& r3, uint32_t a) {
    asm volatile("ldmatrix.sync.aligned.m8n8.x4.shared.b16 {%0,%1,%2,%3}, [%4];"
                 : "=r"(r0), "=r"(r1), "=r"(r2), "=r"(r3) : "r"(a));
}
__device__ __forceinline__ void mma16816(float* c, const uint32_t* a,
                                         const uint32_t* b) {
    asm volatile("mma.sync.aligned.m16n8k16.row.col.f32.bf16.bf16.f32 "
        "{%0,%1,%2,%3}, {%4,%5,%6,%7}, {%8,%9}, {%0,%1,%2,%3};"
        : "+f"(c[0]), "+f"(c[1]), "+f"(c[2]), "+f"(c[3])
        : "r"(a[0]), "r"(a[1]), "r"(a[2]), "r"(a[3]), "r"(b[0]), "r"(b[1]));
}
__device__ __forceinline__ uint32_t pack_bf2(__nv_bfloat16 a, __nv_bfloat16 b) {
    return (uint32_t)__bfloat16_as_ushort(a)
         | ((uint32_t)__bfloat16_as_ushort(b) << 16);
}
__device__ __forceinline__ void bsplit(float v, __nv_bfloat16& h, __nv_bfloat16& l) {
    h = __float2bfloat16(v);
    l = __float2bfloat16(v - __bfloat162float(h));
}
__device__ __forceinline__ void split4(float4 v, uint2& H, uint2& L) {
    __nv_bfloat16 h0, h1, h2, h3, l0, l1, l2, l3;
    bsplit(v.x, h0, l0); bsplit(v.y, h1, l1);
    bsplit(v.z, h2, l2); bsplit(v.w, h3, l3);
    H.x = pack_bf2(h0, h1); H.y = pack_bf2(h2, h3);
    L.x = pack_bf2(l0, l1); L.y = pack_bf2(l2, l3);
}

// ---------------------------------------------------------------------------
// conversions: fp32 -> (hi, lo) bf16
// ---------------------------------------------------------------------------
__global__ __launch_bounds__(256) void conv_x_kernel(const float* __restrict__ x) {
    size_t i = (size_t)blockIdx.x * 256 + threadIdx.x;
    float4 v = ((const float4*)x)[i];
    uint2 H, L;
    split4(v, H, L);
    *(uint2*)&g_xh[4 * i] = H;
    *(uint2*)&g_xl[4 * i] = L;
}
__global__ __launch_bounds__(256) void conv_rw_kernel(const float* __restrict__ rw) {
    size_t i = (size_t)blockIdx.x * 256 + threadIdx.x;
    float4 v = ((const float4*)rw)[i];
    uint2 H, L;
    split4(v, H, L);
    *(uint2*)&g_rwh[4 * i] = H;
    *(uint2*)&g_rwl[4 * i] = L;
}

// ---------------------------------------------------------------------------
// feats via mma.sync: D[n,d] = sum_k x[n,k]*rw[d,k]  (3-term hi/lo bf16)
// CTA tile 128n x 128d, K=256 in 4 chunks of 64, double buffered cp.async.
// 8 warps as 2(m) x 4(n); warp tile 64 x 32. grid (2, 8, 32).
// stage layout: Ah | Al | Bh | Bl  (16KB each, sw128 swizzled 128B rows)
// ---------------------------------------------------------------------------
#define F_SMEM (1024 + 2 * 65536)
__global__ __launch_bounds__(256) void feats_mma_kernel(const float* __restrict__ rb) {
    extern __shared__ char smem[];
    const uint32_t ab = (smem_u32(smem) + 1023) & ~1023u;
    const int tid = threadIdx.x, wid = tid >> 5, lane = tid & 31;
    const int d0 = blockIdx.x * 128;
    const int n0 = blockIdx.y * 128;
    const int br = blockIdx.z, b = br >> 2, r = br & 3;
    const int wm = (wid >> 2) * 64, wn = (wid & 3) * 32;

    auto prefetch = [&](int c, int stage) {
        uint32_t base = ab + stage * 65536;
        for (int u = tid; u < 4096; u += 256) {
            int t = u >> 10, v = u & 1023, row = v >> 3, un = v & 7;
            uint32_t dst = base + t * 16384 + sw128(row * 128 + un * 16);
            const __nv_bfloat16* src;
            if (t < 2) {
                src = (t ? g_xl : g_xh)
                    + (size_t)b * (Nn * DIN) + (size_t)(n0 + row) * DIN + c * 64 + un * 8;
            } else {
                src = (t == 2 ? g_rwh : g_rwl)
                    + (size_t)r * (DOUT * DIN) + (size_t)(d0 + row) * DIN + c * 64 + un * 8;
            }
            CP_ASYNC16(dst, (const char*)src);
        }
        CP_COMMIT();
    };

    float acc[4][4][4] = {};
    const int grp = lane >> 3, l7 = lane & 7;
    const int arow = (grp & 1) * 8 + l7, ac16 = (grp >> 1) * 16;
    const int brow = (grp >> 1) * 8 + l7, bc16 = (grp & 1) * 16;

    prefetch(0, 0);
    for (int c = 0; c < 4; c++) {
        if (c + 1 < 4) { prefetch(c + 1, (c + 1) & 1); CP_WAIT1(); }
        else           { CP_WAIT0(); }
        __syncthreads();
        uint32_t base = ab + (c & 1) * 65536;
        #pragma unroll
        for (int ks = 0; ks < 4; ks++) {
            int kb = ks * 32;
            uint32_t Ah[4][4], Al[4][4], Bh[4][2], Bl[4][2];
            #pragma unroll
            for (int mf = 0; mf < 4; mf++) {
                uint32_t off = sw128((wm + mf * 16 + arow) * 128 + kb + ac16);
                ldsm4(Ah[mf][0], Ah[mf][1], Ah[mf][2], Ah[mf][3], base + off);
                ldsm4(Al[mf][0], Al[mf][1], Al[mf][2], Al[mf][3], base + 16384 + off);
            }
            #pragma unroll
            for (int g = 0; g < 2; g++) {
                uint32_t off = sw128((wn + g * 16 + brow) * 128 + kb + bc16);
                uint32_t t0, t1, t2, t3;
                ldsm4(t0, t1, t2, t3, base + 32768 + off);
                Bh[2*g][0] = t0; Bh[2*g][1] = t1; Bh[2*g+1][0] = t2; Bh[2*g+1][1] = t3;
                ldsm4(t0, t1, t2, t3, base + 49152 + off);
                Bl[2*g][0] = t0; Bl[2*g][1] = t1; Bl[2*g+1][0] = t2; Bl[2*g+1][1] = t3;
            }
            #pragma unroll
            for (int mf = 0; mf < 4; mf++)
                #pragma unroll
                for (int nf = 0; nf < 4; nf++) {
                    mma16816(acc[mf][nf], Ah[mf], Bh[nf]);
                    mma16816(acc[mf][nf], Ah[mf], Bl[nf]);
                    mma16816(acc[mf][nf], Al[mf], Bh[nf]);
                }
        }
        __syncthreads();
    }

    // epilogue: + bias, store fp32
    #pragma unroll
    for (int nf = 0; nf < 4; nf++) {
        int col = d0 + wn + nf * 8 + 2 * (lane & 3);
        float b0 = rb[r * DOUT + col], b1 = rb[r * DOUT + col + 1];
        #pragma unroll
        for (int mf = 0; mf < 4; mf++) {
            int row = n0 + wm + mf * 16 + (lane >> 2);
            float* p0 = g_feats + ((size_t)br * Nn + row) * DOUT + col;
            float* p1 = g_feats + ((size_t)br * Nn + row + 8) * DOUT + col;
            p0[0] = acc[mf][nf][0] + b0; p0[1] = acc[mf][nf][1] + b1;
            p1[0] = acc[mf][nf][2] + b0; p1[1] = acc[mf][nf][3] + b1;
        }
    }
}

// ---------------------------------------------------------------------------
// wf kernel: sj = feats . attn_w[256:], w = exp(sj); write wf^T hi/lo bf16
// ---------------------------------------------------------------------------
__global__ __launch_bounds__(256) void wf_kernel(const float* __restrict__ aw) {
    __shared__ float fs[32][257];
    __shared__ float awj[256];
    __shared__ float wrow[32];
    const int tid = threadIdx.x, wid = tid >> 5, lane = tid & 31;
    const int br = blockIdx.x >> 5, mt = blockIdx.x & 31;
    const int m0 = mt * 32;

    const float* F = g_feats + ((size_t)br * Nn + m0) * DOUT;
    for (int i = tid; i < 32 * 64; i += 256) {
        int row = i >> 6, c4 = i & 63;
        float4 v = ((const float4*)F)[(size_t)row * 64 + c4];
        fs[row][c4 * 4 + 0] = v.x; fs[row][c4 * 4 + 1] = v.y;
        fs[row][c4 * 4 + 2] = v.z; fs[row][c4 * 4 + 3] = v.w;
    }
    awj[tid] = aw[DOUT + tid];
    __syncthreads();

    #pragma unroll
    for (int i = 0; i < 4; i++) {
        int m = wid * 4 + i;
        float s = 0.f;
        #pragma unroll
        for (int k = 0; k < 8; k++)
            s = fmaf(fs[m][lane + k * 32], awj[lane + k * 32], s);
        #pragma unroll
        for (int o = 16; o; o >>= 1) s += __shfl_xor_sync(0xffffffffu, s, o);
        if (lane == 0) {
            float w = __expf(s);
            wrow[m] = w;
            g_w[br * Nn + m0 + m] = w;
        }
    }
    __syncthreads();

    int d = tid;
    __nv_bfloat16 hi[32], lo[32];
    #pragma unroll
    for (int m = 0; m < 32; m++)
        bsplit(fs[m][d] * wrow[m], hi[m], lo[m]);
    __nv_bfloat16* dh = g_wfh + ((size_t)br * DOUT + d) * Nn + m0;
    __nv_bfloat16* dl = g_wfl + ((size_t)br * DOUT + d) * Nn + m0;
    #pragma unroll
    for (int q = 0; q < 4; q++) {
        uint4 vh, vl;
        vh.x = pack_bf2(hi[q*8+0], hi[q*8+1]); vh.y = pack_bf2(hi[q*8+2], hi[q*8+3]);
        vh.z = pack_bf2(hi[q*8+4], hi[q*8+5]); vh.w = pack_bf2(hi[q*8+6], hi[q*8+7]);
        vl.x = pack_bf2(lo[q*8+0], lo[q*8+1]); vl.y = pack_bf2(lo[q*8+2], lo[q*8+3]);
        vl.z = pack_bf2(lo[q*8+4], lo[q*8+5]); vl.w = pack_bf2(lo[q*8+6], lo[q*8+7]);
        *(uint4*)(dh + q * 8) = vh;
        *(uint4*)(dl + q * 8) = vl;
    }
}

// ---------------------------------------------------------------------------
// prepass: adj int32 -> bf16 {0,1}; invZ[br,n] = 1 / sum_m adj[n,m]*w[m]
// ---------------------------------------------------------------------------
__global__ __launch_bounds__(256) void prepass_kernel(const int* __restrict__ adj) {
    __shared__ float ws[Nn];
    const int tid = threadIdx.x, wid = tid >> 5, lane = tid & 31;
    const int br = blockIdx.x >> 5, nb = blockIdx.x & 31;
    for (int i = tid; i < Nn; i += 256) ws[i] = g_w[br * Nn + i];
    __syncthreads();

    #pragma unroll
    for (int i = 0; i < 4; i++) {
        int n = nb * 32 + wid * 4 + i;
        const int4* arow = (const int4*)(adj + (((size_t)br << 10) + n) * Nn);
        __nv_bfloat16* brow = g_adjbf + (((size_t)br << 10) + n) * Nn;
        float z = 0.f;
        #pragma unroll
        for (int k = 0; k < 8; k++) {
            int m = k * 128 + lane * 4;
            int4 a = arow[k * 32 + lane];
            uint2 o;
            o.x = (a.x ? 0x3F80u : 0u) | ((a.y ? 0x3F80u : 0u) << 16);
            o.y = (a.z ? 0x3F80u : 0u) | ((a.w ? 0x3F80u : 0u) << 16);
            *(uint2*)(brow + m) = o;
            if (a.x) z += ws[m];
            if (a.y) z += ws[m + 1];
            if (a.z) z += ws[m + 2];
            if (a.w) z += ws[m + 3];
        }
        #pragma unroll
        for (int o = 16; o; o >>= 1) z += __shfl_xor_sync(0xffffffffu, z, o);
        if (lane == 0) g_invZ[(br << 10) + n] = 1.0f / z;
    }
}

// ---------------------------------------------------------------------------
// agg via mma.sync: out[b,n,d] = sum_r invZ[r,n] * (adj_r @ wf_r^T)[n,d]
// CTA tile 128n x 128d; per r: K=1024 in 16 chunks of 64 (2-term hi/lo B).
// 8 warps 2x4, warp tile 64x32. grid (2, 8, 8).
// stage: A | Bh | Bl (16KB each), double buffered.
// ---------------------------------------------------------------------------
#define A_SMEM (1024 + 2 * 49152)
__global__ __launch_bounds__(256) void agg_mma_kernel(float* __restrict__ out) {
    extern __shared__ char smem[];
    __shared__ float izs[Rr * 128];
    const uint32_t ab = (smem_u32(smem) + 1023) & ~1023u;
    const int tid = threadIdx.x, wid = tid >> 5, lane = tid & 31;
    const int d0 = blockIdx.x * 128;
    const int n0 = blockIdx.y * 128;
    const int b  = blockIdx.z;
    const int wm = (wid >> 2) * 64, wn = (wid & 3) * 32;

    for (int i = tid; i < Rr * 128; i += 256)
        izs[i] = g_invZ[((b * Rr + (i >> 7)) << 10) + n0 + (i & 127)];

    auto prefetch = [&](int c, int stage) {
        int r = c >> 4, kc = c & 15, m0 = kc * 64;
        uint32_t base = ab + stage * 49152;
        size_t brr = (size_t)(b * Rr + r);
        for (int u = tid; u < 3072; u += 256) {
            int t = u >> 10, v = u & 1023, row = v >> 3, un = v & 7;
            uint32_t dst = base + t * 16384 + sw128(row * 128 + un * 16);
            const __nv_bfloat16* src;
            if (t == 0)      src = g_adjbf + (brr * Nn + n0 + row) * Nn + m0 + un * 8;
            else if (t == 1) src = g_wfh + (brr * DOUT + d0 + row) * Nn + m0 + un * 8;
            else             src = g_wfl + (brr * DOUT + d0 + row) * Nn + m0 + un * 8;
            CP_ASYNC16(dst, (const char*)src);
        }
        CP_COMMIT();
    };

    float total[4][4][4] = {};
    float acc[4][4][4] = {};
    const int grp = lane >> 3, l7 = lane & 7;
    const int arow = (grp & 1) * 8 + l7, ac16 = (grp >> 1) * 16;
    const int brow = (grp >> 1) * 8 + l7, bc16 = (grp & 1) * 16;
    const int T = 64;

    prefetch(0, 0);
    for (int c = 0; c < T; c++) {
        if (c + 1 < T) { prefetch(c + 1, (c + 1) & 1); CP_WAIT1(); }
        else           { CP_WAIT0(); }
        __syncthreads();
        uint32_t base = ab + (c & 1) * 49152;
        #pragma unroll
        for (int ks = 0; ks < 4; ks++) {
            int kb = ks * 32;
            uint32_t A[4][4], Bh[4][2], Bl[4][2];
            #pragma unroll
            for (int mf = 0; mf < 4; mf++) {
                uint32_t off = sw128((wm + mf * 16 + arow) * 128 + kb + ac16);
                ldsm4(A[mf][0], A[mf][1], A[mf][2], A[mf][3], base + off);
            }
            #pragma unroll
            for (int g = 0; g < 2; g++) {
                uint32_t off = sw128((wn + g * 16 + brow) * 128 + kb + bc16);
                uint32_t t0, t1, t2, t3;
                ldsm4(t0, t1, t2, t3, base + 16384 + off);
                Bh[2*g][0] = t0; Bh[2*g][1] = t1; Bh[2*g+1][0] = t2; Bh[2*g+1][1] = t3;
                ldsm4(t0, t1, t2, t3, base + 32768 + off);
                Bl[2*g][0] = t0; Bl[2*g][1] = t1; Bl[2*g+1][0] = t2; Bl[2*g+1][1] = t3;
            }
            #pragma unroll
            for (int mf = 0; mf < 4; mf++)
                #pragma unroll
                for (int nf = 0; nf < 4; nf++) {
                    mma16816(acc[mf][nf], A[mf], Bh[nf]);
                    mma16816(acc[mf][nf], A[mf], Bl[nf]);
                }
        }
        __syncthreads();

        if ((c & 15) == 15) {            // end of relation r: fold with invZ
            int r = c >> 4;
            #pragma unroll
            for (int mf = 0; mf < 4; mf++) {
                float iz0 = izs[r * 128 + wm + mf * 16 + (lane >> 2)];
                float iz1 = izs[r * 128 + wm + mf * 16 + (lane >> 2) + 8];
                #pragma unroll
                for (int nf = 0; nf < 4; nf++) {
                    total[mf][nf][0] = fmaf(iz0, acc[mf][nf][0], total[mf][nf][0]);
                    total[mf][nf][1] = fmaf(iz0, acc[mf][nf][1], total[mf][nf][1]);
                    total[mf][nf][2] = fmaf(iz1, acc[mf][nf][2], total[mf][nf][2]);
                    total[mf][nf][3] = fmaf(iz1, acc[mf][nf][3], total[mf][nf][3]);
                    acc[mf][nf][0] = 0.f; acc[mf][nf][1] = 0.f;
                    acc[mf][nf][2] = 0.f; acc[mf][nf][3] = 0.f;
                }
            }
        }
    }

    #pragma unroll
    for (int nf = 0; nf < 4; nf++) {
        int col = d0 + wn + nf * 8 + 2 * (lane & 3);
        #pragma unroll
        for (int mf = 0; mf < 4; mf++) {
            int row = n0 + wm + mf * 16 + (lane >> 2);
            float* p0 = out + ((size_t)b * Nn + row) * DOUT + col;
            float* p1 = out + ((size_t)b * Nn + row + 8) * DOUT + col;
            p0[0] = total[mf][nf][0]; p0[1] = total[mf][nf][1];
            p1[0] = total[mf][nf][2]; p1[1] = total[mf][nf][3];
        }
    }
}

// ---------------------------------------------------------------------------
// gate epilogue: out = sigmoid(out . gw + gb) * out, one block per (b,n)
// ---------------------------------------------------------------------------
__global__ __launch_bounds__(256) void gate_kernel(
    float* __restrict__ out, const float* __restrict__ gw,
    const float* __restrict__ gb_p)
{
    __shared__ float red[8];
    float* o = out + (size_t)blockIdx.x * DOUT;
    int t = threadIdx.x, lane = t & 31;
    float a = o[t];
    float v = a * gw[t];
    #pragma unroll
    for (int off = 16; off; off >>= 1) v += __shfl_xor_sync(0xffffffffu, v, off);
    if (lane == 0) red[t >> 5] = v;
    __syncthreads();
    if (t < 32) {
        float r = (t < 8) ? red[t] : 0.0f;
        #pragma unroll
        for (int off = 4; off; off >>= 1) r += __shfl_xor_sync(0xffffffffu, r, off);
        if (t == 0) red[0] = r;
    }
    __syncthreads();
    float g = 1.0f / (1.0f + __expf(-(red[0] + gb_p[0])));
    o[t] = g * a;
}

// ---------------------------------------------------------------------------
extern "C" void kernel_launch(void* const* d_in, const int* in_sizes, int n_in,
                              void* d_out, int out_size)
{
    const float* x   = (const float*)d_in[0];
    const int*   adj = (const int*)  d_in[1];
    const float* rw  = (const float*)d_in[2];
    const float* rb  = (const float*)d_in[3];
    const float* aw  = (const float*)d_in[4];
    const float* gw  = (const float*)d_in[6];
    const float* gb  = (const float*)d_in[7];
    float* out = (float*)d_out;

    cudaFuncSetAttribute(feats_mma_kernel,
                         cudaFuncAttributeMaxDynamicSharedMemorySize, F_SMEM);
    cudaFuncSetAttribute(agg_mma_kernel,
                         cudaFuncAttributeMaxDynamicSharedMemorySize, A_SMEM);

    conv_x_kernel<<<(Bq * Nn * DIN / 4) / 256, 256>>>(x);
    conv_rw_kernel<<<(Rr * DOUT * DIN / 4) / 256, 256>>>(rw);

    feats_mma_kernel<<<dim3(2, 8, Bq * Rr), 256, F_SMEM>>>(rb);

    wf_kernel<<<Bq * Rr * 32, 256>>>(aw);

    prepass_kernel<<<Bq * Rr * 32, 256>>>(adj);

    agg_mma_kernel<<<dim3(2, 8, Bq), 256, A_SMEM>>>(out);

    gate_kernel<<<Bq * Nn, 256>>>(out, gw, gb);
}